// round 16
// baseline (speedup 1.0000x reference)
#include <cuda_runtime.h>
#include <cuda_bf16.h>
#include <cuda_fp16.h>
#include <cstdint>

#define NTOT 65536
#define DDIM 512
#define KCL  64

#define BN 64               // d-columns per CTA tile
#define BK 32               // k rows per stage
#define DTILES 8            // DDIM / BN
#define NCHUNKS 74          // grid = 8*74 = 592 CTAs = 4 CTAs/SM, one wave
#define NCTAS (DTILES * NCHUNKS)

// f32 staging ring (cp.async target), depth 2, unpadded 256B rows
#define ROW32 256
#define STG32 (2 * BK * ROW32)          // 16384 B per stage (F 8K + H 8K)
#define H32_OFF (BK * ROW32)            // 8192

// f16 ring (LDSM source), depth 2 — R15 layout
#define SF_B 144
#define SH_B 144
#define SLOT16 (BK * (SF_B + SH_B))     // 9216 B
#define H16_OFF (BK * SF_B)             // 4608

#define OFF16 (2 * STG32)               // 32768
#define SMEM_DYN (OFF16 + 2 * SLOT16)   // 51200 B

__device__ float        g_partial[KCL * DDIM];  // .bss zero; re-zeroed per call
__device__ float        g_h2sum;
__device__ unsigned int g_count;

__device__ __forceinline__ uint32_t smem_u32(const void* p) {
    return (uint32_t)__cvta_generic_to_shared(p);
}

__device__ __forceinline__ uint32_t pack_f16(float lo, float hi) {
    uint32_t r;
    asm("cvt.rn.f16x2.f32 %0, %1, %2;" : "=r"(r) : "f"(hi), "f"(lo));
    return r;
}

__device__ __forceinline__ void cp16(uint32_t s, const void* g) {
    asm volatile("cp.async.cg.shared.global [%0], [%1], 16;" :: "r"(s), "l"(g));
}
#define CP_COMMIT() asm volatile("cp.async.commit_group;")
#define CP_WAIT(n)  asm volatile("cp.async.wait_group %0;" :: "n"(n))

__device__ __forceinline__ void ldsm4t(uint32_t* r, uint32_t addr) {
    asm volatile(
        "ldmatrix.sync.aligned.m8n8.x4.trans.shared.b16 {%0,%1,%2,%3}, [%4];"
        : "=r"(r[0]), "=r"(r[1]), "=r"(r[2]), "=r"(r[3]) : "r"(addr));
}

__global__ __launch_bounds__(256, 4)
void k_fused(const float* __restrict__ H, const float* __restrict__ Fm,
             float* __restrict__ out) {
    extern __shared__ __align__(16) char dsm[];
    __shared__ float        redbuf[8];
    __shared__ double       sb[8];
    __shared__ unsigned int s_ticket;

    const uint32_t dynb = smem_u32(dsm);
    const int tid  = threadIdx.x;
    const int lane = tid & 31;
    const int wid  = tid >> 5;
    const int d0   = blockIdx.x * BN;
    const int c    = blockIdx.y;

    // 2048 k-blocks over 74 chunks: chunks 0..49 get 28, 50..73 get 27
    const int kb_start = c * 27 + (c < 50 ? c : 50);
    const int ITERS    = 27 + (c < 50 ? 1 : 0);
    const int nb0      = kb_start * BK;

    const int wm = (wid >> 1) * 16;     // 4 warp rows along m
    const int wn = (wid & 1) * 32;      // 2 warp cols along n
    const int g  = lane >> 2;
    const int t  = lane & 3;

    // chunk mapping (used by both cp.async and convert): idx = tid + 256j
    const int r0 = tid >> 4;            // row for j=0 (0..15)
    const int q  = tid & 15;            // 16B chunk within row

    // LDSM per-lane offsets — R15-proven
    const uint32_t a_lane = (uint32_t)(((lane >> 4) & 1) * (8 * SF_B)
                                       + (lane & 7) * SF_B
                                       + ((lane >> 3) & 1) * 16);
    const uint32_t b_lane = (uint32_t)(((lane >> 3) & 1) * (8 * SH_B)
                                       + (lane & 7) * SH_B
                                       + ((lane >> 4) & 1) * 16);

    uint32_t acc[4][2];                 // f16x2 accumulators (R15-proven)
#pragma unroll
    for (int a = 0; a < 4; a++) { acc[a][0] = 0u; acc[a][1] = 0u; }

    float h2 = 0.f;

    // ---- producer: cp.async one stage (its stage index selects ring slot) ----
    auto issue = [&](int it) {
        const uint32_t st = dynb + (it & 1) * STG32;
        const int nb = nb0 + it * BK;
#pragma unroll
        for (int j = 0; j < 2; j++) {
            const int r = r0 + 16 * j;
            cp16(st + r * ROW32 + q * 16, &Fm[(size_t)(nb + r) * KCL + q * 4]);
            cp16(st + H32_OFF + r * ROW32 + q * 16,
                 &H[(size_t)(nb + r) * DDIM + d0 + q * 4]);
        }
        CP_COMMIT();
    };

    // ---- convert: each thread converts exactly the chunks it cp'd ----
    auto convert = [&](int it) {
        const char* st = dsm + (it & 1) * STG32;
        char* f16s = dsm + OFF16 + (it & 1) * SLOT16;
#pragma unroll
        for (int j = 0; j < 2; j++) {
            const int r = r0 + 16 * j;
            float4 fv = *(const float4*)(st + r * ROW32 + q * 16);
            *(uint2*)(f16s + r * SF_B + q * 8) =
                make_uint2(pack_f16(fv.x, fv.y), pack_f16(fv.z, fv.w));
            float4 hv = *(const float4*)(st + H32_OFF + r * ROW32 + q * 16);
            *(uint2*)(f16s + H16_OFF + r * SH_B + q * 8) =
                make_uint2(pack_f16(hv.x, hv.y), pack_f16(hv.z, hv.w));
            h2 = fmaf(hv.x, hv.x, h2);
            h2 = fmaf(hv.y, hv.y, h2);
            h2 = fmaf(hv.z, hv.z, h2);
            h2 = fmaf(hv.w, hv.w, h2);
        }
    };

    auto compute = [&](int it) {
        const uint32_t base  = dynb + OFF16 + (it & 1) * SLOT16;
        const uint32_t aBase = base + (uint32_t)(wm * 2) + a_lane;
        const uint32_t bBase = base + H16_OFF + (uint32_t)(wn * 2) + b_lane;
#pragma unroll
        for (int ks = 0; ks < 2; ks++) {
            uint32_t a[4], b[2][4];
            ldsm4t(a, aBase + ks * (16 * SF_B));
            ldsm4t(b[0], bBase + ks * (16 * SH_B));
            ldsm4t(b[1], bBase + ks * (16 * SH_B) + 32);
#pragma unroll
            for (int ni = 0; ni < 4; ni++) {
                const uint32_t b0 = b[ni >> 1][(ni & 1) * 2];
                const uint32_t b1 = b[ni >> 1][(ni & 1) * 2 + 1];
                asm volatile(
                    "mma.sync.aligned.m16n8k16.row.col.f16.f16.f16.f16 "
                    "{%0,%1}, {%2,%3,%4,%5}, {%6,%7}, {%0,%1};\n"
                    : "+r"(acc[ni][0]), "+r"(acc[ni][1])
                    : "r"(a[0]), "r"(a[1]), "r"(a[2]), "r"(a[3]),
                      "r"(b0), "r"(b1));
            }
        }
    };

    // ---- pipeline: cp depth 2, f16 ring depth 2, one barrier per stage ----
    issue(0);
    issue(1);
    CP_WAIT(1);          // stage 0 retired (stage 1 still in flight)
    convert(0);
    __syncthreads();     // f16 slot 0 published

#pragma unroll 1
    for (int it = 0; it < ITERS; ++it) {
        if (it + 2 < ITERS) issue(it + 2);   // f32 slot it&1: converted at it-1
        if (it + 1 < ITERS) {
            CP_WAIT(1);                      // retire stage it+1; it+2 in flight
            convert(it + 1);                 // f16 slot (it+1)&1
        }
        compute(it);                         // f16 slot it&1
        __syncthreads();                     // publish (it+1); guard slot reuse
    }

    // ---- epilogue: unpack f16 acc, packed float2 L2 atomics (R15) ----
#pragma unroll
    for (int ni = 0; ni < 4; ni++) {
        int m = wm + g;
        int n = d0 + wn + ni * 8 + 2 * t;
        __half2 c0 = *reinterpret_cast<__half2*>(&acc[ni][0]);
        __half2 c1 = *reinterpret_cast<__half2*>(&acc[ni][1]);
        atomicAdd((float2*)&g_partial[m * DDIM + n],
                  make_float2(__low2float(c0), __high2float(c0)));
        atomicAdd((float2*)&g_partial[(m + 8) * DDIM + n],
                  make_float2(__low2float(c1), __high2float(c1)));
    }

    // ---- h2 block reduce, one atomic per CTA ----
#pragma unroll
    for (int o = 16; o > 0; o >>= 1) h2 += __shfl_xor_sync(0xffffffffu, h2, o);
    if (lane == 0) redbuf[wid] = h2;
    __syncthreads();
    if (tid == 0) {
        float s = 0.f;
#pragma unroll
        for (int w = 0; w < 8; w++) s += redbuf[w];
        atomicAdd(&g_h2sum, s);
    }

    // ---- last-CTA finalize: square-sum G, write scalar, reset state ----
    __threadfence();
    if (tid == 0) s_ticket = atomicAdd(&g_count, 1u);
    __syncthreads();
    if (s_ticket != NCTAS - 1) return;

    double s = 0.0;
    for (int i = tid; i < KCL * DDIM; i += 256) {
        float v = __ldcg(&g_partial[i]);
        s += (double)v * (double)v;
        g_partial[i] = 0.f;              // re-zero for next graph replay
    }
#pragma unroll
    for (int o = 16; o > 0; o >>= 1) s += __shfl_xor_sync(0xffffffffu, s, o);
    if (lane == 0) sb[wid] = s;
    __syncthreads();
    if (tid == 0) {
        double tot = 0.0;
#pragma unroll
        for (int w = 0; w < 8; w++) tot += sb[w];
        float h2tot = __ldcg(&g_h2sum);
        out[0] = (float)((double)h2tot - tot);
        g_h2sum = 0.f;
        g_count = 0u;
    }
}

extern "C" void kernel_launch(void* const* d_in, const int* in_sizes, int n_in,
                              void* d_out, int out_size) {
    const float* Hp;
    const float* Fp;
    if (in_sizes[0] == NTOT * DDIM) {
        Hp = (const float*)d_in[0];
        Fp = (const float*)d_in[1];
    } else {
        Hp = (const float*)d_in[1];
        Fp = (const float*)d_in[0];
    }

    cudaFuncSetAttribute(k_fused, cudaFuncAttributeMaxDynamicSharedMemorySize,
                         SMEM_DYN);
    dim3 grid(DTILES, NCHUNKS);
    k_fused<<<grid, 256, SMEM_DYN>>>(Hp, Fp, (float*)d_out);
}